// round 10
// baseline (speedup 1.0000x reference)
#include <cuda_runtime.h>
#include <cuda_bf16.h>
#include <cstdint>

#define Nn   50000
#define Ee   600000
#define IND  384
#define HIDD 128
#define HYPD 256

// ---------------- scratch (static device globals; no runtime allocation) ----------------
__device__ __align__(128) float g_xemb[(size_t)Nn * HIDD];
__device__ __align__(128) float g_cur [(size_t)Nn * HIDD];
__device__ __align__(128) float g_nxt [(size_t)Nn * HIDD];
__device__ __align__(128) float g_acc [(size_t)Nn * HIDD];
__device__ __align__(128) float g_Hm  [(size_t)Nn * HYPD];
__device__ __align__(128) float g_lat [HYPD * HIDD];
__device__ __align__(128) int   g_deg [Nn];
__device__ __align__(128) float g_dinv[Nn];
__device__ __align__(128) int   g_rowptr[Nn + 1];
__device__ __align__(128) int   g_fill[Nn];
__device__ __align__(128) int   g_col [Ee];
__device__ __align__(128) float g_val [Ee];
__device__ __align__(128) int   g_bsum[256];

// ---------------- init: zero deg / fill / lat ----------------
__global__ void init_k() {
    int i = blockIdx.x * blockDim.x + threadIdx.x;
    if (i < Nn) { g_deg[i] = 0; g_fill[i] = 0; }
    if (i < HYPD * HIDD) g_lat[i] = 0.f;
}

__global__ void deg_k(const int* __restrict__ dst) {
    int e = blockIdx.x * blockDim.x + threadIdx.x;
    if (e < Ee) atomicAdd(&g_deg[dst[e]], 1);
}

__global__ void dinv_k() {
    int i = blockIdx.x * blockDim.x + threadIdx.x;
    if (i < Nn) {
        int d = g_deg[i];
        g_dinv[i] = (d > 0) ? rsqrtf((float)d) : 0.f;
    }
}

// ---------------- 3-kernel exclusive scan over g_deg -> g_rowptr ----------------
__global__ void scan1_k() {
    __shared__ int sm[256];
    int t = threadIdx.x;
    int i = blockIdx.x * 256 + t;
    int v = (i < Nn) ? g_deg[i] : 0;
    sm[t] = v;
    __syncthreads();
    #pragma unroll
    for (int o = 1; o < 256; o <<= 1) {
        int add = (t >= o) ? sm[t - o] : 0;
        __syncthreads();
        sm[t] += add;
        __syncthreads();
    }
    if (i < Nn) g_rowptr[i] = sm[t] - v;
    if (t == 255) g_bsum[blockIdx.x] = sm[255];
}

__global__ void scan2_k(int nb) {
    if (threadIdx.x == 0 && blockIdx.x == 0) {
        int run = 0;
        for (int b = 0; b < nb; b++) { int tmp = g_bsum[b]; g_bsum[b] = run; run += tmp; }
    }
}

__global__ void scan3_k() {
    int i = blockIdx.x * blockDim.x + threadIdx.x;
    if (i < Nn) g_rowptr[i] += g_bsum[i >> 8];
    if (i == 0) g_rowptr[Nn] = Ee;
}

__global__ void fill_k(const int* __restrict__ src, const int* __restrict__ dst) {
    int e = blockIdx.x * blockDim.x + threadIdx.x;
    if (e >= Ee) return;
    int s = src[e], d = dst[e];
    int p = g_rowptr[d] + atomicAdd(&g_fill[d], 1);
    g_col[p] = s;
    g_val[p] = g_dinv[s] * g_dinv[d];
}

// =====================================================================
// Tensor-core GEMM via base-ISA mma.sync (bf16 hi/lo split, fp32 acc).
// C[M,N] = A @ B, B global layout [K,N].
// flags: 1 = relu, 2 = transA (A[m,k] = Aglob[k, rowBase+m]), 4 = atomic C
// gridDim.z = K-split count (use with flag 4).
// Tile: BM=128, BN=128, BK=32. 8 warps (4 mrow x 2 ncol), warp = 32x64.
// =====================================================================

__device__ __forceinline__ void mma16816(float* c,
    uint32_t a0, uint32_t a1, uint32_t a2, uint32_t a3,
    uint32_t b0, uint32_t b1)
{
    asm volatile(
        "mma.sync.aligned.m16n8k16.row.col.f32.bf16.bf16.f32 "
        "{%0,%1,%2,%3}, {%4,%5,%6,%7}, {%8,%9}, {%0,%1,%2,%3};"
        : "+f"(c[0]), "+f"(c[1]), "+f"(c[2]), "+f"(c[3])
        : "r"(a0), "r"(a1), "r"(a2), "r"(a3), "r"(b0), "r"(b1));
}

__device__ __forceinline__ void split_hl(float v, unsigned short& hi, unsigned short& lo) {
    uint32_t b = __float_as_uint(v);
    uint32_t hb = b & 0xFFFF0000u;
    hi = (unsigned short)(b >> 16);
    lo = __bfloat16_as_ushort(__float2bfloat16(v - __uint_as_float(hb)));
}

#define APAD 8   // row pad (bf16 units): row stride 40 bf16 = 80B = 20 banks -> conflict-free frag loads

__global__ __launch_bounds__(256)
void gemm_mma_k(const float* __restrict__ A, const float* __restrict__ B,
                const float* __restrict__ bias, float* __restrict__ C,
                float* __restrict__ C2, int M, int N, int K, int ldA, int flags)
{
    __shared__ __nv_bfloat16 As[2][128][32 + APAD];  // [hi/lo][m][k]
    __shared__ __nv_bfloat16 Bs[2][128][32 + APAD];  // [hi/lo][n][k]

    const int tid = threadIdx.x;
    const int wid = tid >> 5, lane = tid & 31;
    const int wm = wid >> 1;          // 0..3 : 32-row band
    const int wn = wid & 1;           // 0..1 : 64-col band
    const int g  = lane >> 2;         // fragment group row 0..7
    const int tg = lane & 3;          // fragment thread-in-group

    const int rowBase = blockIdx.x * 128;
    const int colBase = blockIdx.y * 128;
    const int nz = gridDim.z;
    const int kPer = (K + nz - 1) / nz;
    const int k0g = blockIdx.z * kPer;
    const int k1g = min(k0g + kPer, K);

    float c[2][8][4];
    #pragma unroll
    for (int mt = 0; mt < 2; mt++)
        #pragma unroll
        for (int nt = 0; nt < 8; nt++)
            #pragma unroll
            for (int q = 0; q < 4; q++) c[mt][nt][q] = 0.f;

    for (int k0 = k0g; k0 < k1g; k0 += 32) {
        // ---------------- A tile fill ----------------
        if (flags & 2) {
            // A[m][k] = Aglob[k][rowBase+m]; column reads, contiguous across threads in m
            int m  = tid & 127;
            int kh = (tid >> 7) * 16;
            uint32_t hp[8], lp[8];
            #pragma unroll
            for (int j = 0; j < 16; j++) {
                int gk = k0 + kh + j;
                float v = (gk < k1g) ? A[(size_t)gk * ldA + rowBase + m] : 0.f;
                unsigned short h, l; split_hl(v, h, l);
                if ((j & 1) == 0) { hp[j >> 1] = h; lp[j >> 1] = l; }
                else { hp[j >> 1] |= (uint32_t)h << 16; lp[j >> 1] |= (uint32_t)l << 16; }
            }
            *(uint4*)&As[0][m][kh]     = make_uint4(hp[0], hp[1], hp[2], hp[3]);
            *(uint4*)&As[0][m][kh + 8] = make_uint4(hp[4], hp[5], hp[6], hp[7]);
            *(uint4*)&As[1][m][kh]     = make_uint4(lp[0], lp[1], lp[2], lp[3]);
            *(uint4*)&As[1][m][kh + 8] = make_uint4(lp[4], lp[5], lp[6], lp[7]);
        } else {
            // natural row-major: 128 rows x 8 float4
            #pragma unroll
            for (int i = 0; i < 4; i++) {
                int f = tid + i * 256;
                int r = f >> 3, q = f & 7;
                int grow = rowBase + r;
                float4 v = make_float4(0.f, 0.f, 0.f, 0.f);
                if (grow < M && (k0 + q * 4 + 3) < k1g)
                    v = *(const float4*)(A + (size_t)grow * ldA + k0 + q * 4);
                unsigned short h0,h1,h2,h3,l0,l1,l2,l3;
                split_hl(v.x,h0,l0); split_hl(v.y,h1,l1);
                split_hl(v.z,h2,l2); split_hl(v.w,h3,l3);
                *(uint2*)&As[0][r][q*4] = make_uint2(h0 | ((uint32_t)h1<<16), h2 | ((uint32_t)h3<<16));
                *(uint2*)&As[1][r][q*4] = make_uint2(l0 | ((uint32_t)l1<<16), l2 | ((uint32_t)l3<<16));
            }
        }
        // ---------------- B tile fill (transpose to [n][k]) ----------------
        {
            int n  = tid & 127;
            int kh = (tid >> 7) * 16;
            uint32_t hp[8], lp[8];
            #pragma unroll
            for (int j = 0; j < 16; j++) {
                int gk = k0 + kh + j;
                float v = (gk < k1g) ? B[(size_t)gk * N + colBase + n] : 0.f;
                unsigned short h, l; split_hl(v, h, l);
                if ((j & 1) == 0) { hp[j >> 1] = h; lp[j >> 1] = l; }
                else { hp[j >> 1] |= (uint32_t)h << 16; lp[j >> 1] |= (uint32_t)l << 16; }
            }
            *(uint4*)&Bs[0][n][kh]     = make_uint4(hp[0], hp[1], hp[2], hp[3]);
            *(uint4*)&Bs[0][n][kh + 8] = make_uint4(hp[4], hp[5], hp[6], hp[7]);
            *(uint4*)&Bs[1][n][kh]     = make_uint4(lp[0], lp[1], lp[2], lp[3]);
            *(uint4*)&Bs[1][n][kh + 8] = make_uint4(lp[4], lp[5], lp[6], lp[7]);
        }
        __syncthreads();

        // ---------------- compute: 2 k16 steps ----------------
        #pragma unroll
        for (int kk = 0; kk < 2; kk++) {
            const int kb = kk * 16 + tg * 2;
            uint32_t ah[2][4], al[2][4];
            #pragma unroll
            for (int mt = 0; mt < 2; mt++) {
                int r0 = wm * 32 + mt * 16 + g;
                ah[mt][0] = *(const uint32_t*)&As[0][r0    ][kb];
                ah[mt][1] = *(const uint32_t*)&As[0][r0 + 8][kb];
                ah[mt][2] = *(const uint32_t*)&As[0][r0    ][kb + 8];
                ah[mt][3] = *(const uint32_t*)&As[0][r0 + 8][kb + 8];
                al[mt][0] = *(const uint32_t*)&As[1][r0    ][kb];
                al[mt][1] = *(const uint32_t*)&As[1][r0 + 8][kb];
                al[mt][2] = *(const uint32_t*)&As[1][r0    ][kb + 8];
                al[mt][3] = *(const uint32_t*)&As[1][r0 + 8][kb + 8];
            }
            #pragma unroll
            for (int nt = 0; nt < 8; nt++) {
                int nr = wn * 64 + nt * 8 + g;
                uint32_t bh0 = *(const uint32_t*)&Bs[0][nr][kb];
                uint32_t bh1 = *(const uint32_t*)&Bs[0][nr][kb + 8];
                uint32_t bl0 = *(const uint32_t*)&Bs[1][nr][kb];
                uint32_t bl1 = *(const uint32_t*)&Bs[1][nr][kb + 8];
                #pragma unroll
                for (int mt = 0; mt < 2; mt++) {
                    mma16816(c[mt][nt], ah[mt][0], ah[mt][1], ah[mt][2], ah[mt][3], bh0, bh1);
                    mma16816(c[mt][nt], al[mt][0], al[mt][1], al[mt][2], al[mt][3], bh0, bh1);
                    mma16816(c[mt][nt], ah[mt][0], ah[mt][1], ah[mt][2], ah[mt][3], bl0, bl1);
                }
            }
        }
        __syncthreads();
    }

    // ---------------- epilogue ----------------
    const bool doRelu = (flags & 1), doAtom = (flags & 4);
    #pragma unroll
    for (int mt = 0; mt < 2; mt++) {
        #pragma unroll
        for (int half = 0; half < 2; half++) {
            int grow = rowBase + wm * 32 + mt * 16 + g + half * 8;
            if (grow >= M) continue;
            #pragma unroll
            for (int nt = 0; nt < 8; nt++) {
                int col = colBase + wn * 64 + nt * 8 + tg * 2;
                float v0 = c[mt][nt][half * 2 + 0];
                float v1 = c[mt][nt][half * 2 + 1];
                if (doAtom) {
                    atomicAdd(C + (size_t)grow * N + col,     v0);
                    atomicAdd(C + (size_t)grow * N + col + 1, v1);
                } else {
                    if (bias) { v0 += bias[col]; v1 += bias[col + 1]; }
                    if (doRelu) { v0 = fmaxf(v0, 0.f); v1 = fmaxf(v1, 0.f); }
                    float2 o = make_float2(v0, v1);
                    *(float2*)(C + (size_t)grow * N + col) = o;
                    if (C2) *(float2*)(C2 + (size_t)grow * N + col) = o;
                }
            }
        }
    }
}

// ---------------- gumbel-softmax over HYP=256 (warp per row, in-place on g_Hm) ----------------
__global__ void softmax_k(const float* __restrict__ gum) {
    int row  = (blockIdx.x * blockDim.x + threadIdx.x) >> 5;
    int lane = threadIdx.x & 31;
    if (row >= Nn) return;
    const float* lrow = g_Hm + (size_t)row * HYPD;
    const float* urow = gum  + (size_t)row * HYPD;
    float t[8];
    #pragma unroll
    for (int q = 0; q < 2; q++) {
        float4 lg = *(const float4*)(lrow + lane * 8 + q * 4);
        float4 uu = *(const float4*)(urow + lane * 8 + q * 4);
        t[q*4+0] = (lg.x - logf(-logf(uu.x + 1e-10f) + 1e-10f)) * 2.f;
        t[q*4+1] = (lg.y - logf(-logf(uu.y + 1e-10f) + 1e-10f)) * 2.f;
        t[q*4+2] = (lg.z - logf(-logf(uu.z + 1e-10f) + 1e-10f)) * 2.f;
        t[q*4+3] = (lg.w - logf(-logf(uu.w + 1e-10f) + 1e-10f)) * 2.f;
    }
    float m = t[0];
    #pragma unroll
    for (int j = 1; j < 8; j++) m = fmaxf(m, t[j]);
    #pragma unroll
    for (int o = 16; o; o >>= 1) m = fmaxf(m, __shfl_xor_sync(0xffffffffu, m, o));
    float s = 0.f;
    #pragma unroll
    for (int j = 0; j < 8; j++) { t[j] = expf(t[j] - m); s += t[j]; }
    #pragma unroll
    for (int o = 16; o; o >>= 1) s += __shfl_xor_sync(0xffffffffu, s, o);
    float inv = 1.f / s;
    float* orow = g_Hm + (size_t)row * HYPD;
    #pragma unroll
    for (int q = 0; q < 2; q++) {
        float4 v = make_float4(t[q*4+0]*inv, t[q*4+1]*inv, t[q*4+2]*inv, t[q*4+3]*inv);
        *(float4*)(orow + lane * 8 + q * 4) = v;
    }
}

// ---------------- LightGCN propagation: warp per dst row, CSR gather ----------------
__global__ void prop_k(const float* __restrict__ cur, float* __restrict__ nxt) {
    int row  = (blockIdx.x * blockDim.x + threadIdx.x) >> 5;
    int lane = threadIdx.x & 31;
    if (row >= Nn) return;
    int s = g_rowptr[row], e = g_rowptr[row + 1];
    float4 a = make_float4(0.f, 0.f, 0.f, 0.f);
    for (int p = s; p < e; p++) {
        float w = g_val[p];
        int   c = g_col[p];
        float4 v = *(const float4*)(cur + (size_t)c * HIDD + lane * 4);
        a.x += w * v.x; a.y += w * v.y; a.z += w * v.z; a.w += w * v.w;
    }
    size_t off = (size_t)row * HIDD + lane * 4;
    *(float4*)(nxt + off) = a;
    float4 ac = *(float4*)(g_acc + off);
    ac.x += a.x; ac.y += a.y; ac.z += a.z; ac.w += a.w;
    *(float4*)(g_acc + off) = ac;
}

// ---------------- final = acc/4 + alpha * hyper/||hyper||  (warp per row) ----------------
__global__ void final_k(float* __restrict__ out) {
    int row  = (blockIdx.x * blockDim.x + threadIdx.x) >> 5;
    int lane = threadIdx.x & 31;
    if (row >= Nn) return;
    size_t off = (size_t)row * HIDD + lane * 4;
    float4 h = *(const float4*)(g_nxt + off);
    float ss = h.x * h.x + h.y * h.y + h.z * h.z + h.w * h.w;
    #pragma unroll
    for (int o = 16; o; o >>= 1) ss += __shfl_xor_sync(0xffffffffu, ss, o);
    float inv = 0.1f / fmaxf(sqrtf(ss), 1e-12f);
    float4 a = *(const float4*)(g_acc + off);
    float4 r;
    r.x = a.x * 0.25f + h.x * inv;
    r.y = a.y * 0.25f + h.y * inv;
    r.z = a.z * 0.25f + h.z * inv;
    r.w = a.w * 0.25f + h.w * inv;
    *(float4*)(out + off) = r;
}

// ---------------- launcher ----------------
extern "C" void kernel_launch(void* const* d_in, const int* in_sizes, int n_in,
                              void* d_out, int out_size) {
    const float* x       = (const float*)d_in[0];
    const int*   ei      = (const int*)  d_in[1];
    const float* gum     = (const float*)d_in[2];
    const float* w_feat  = (const float*)d_in[3];
    const float* b_feat  = (const float*)d_in[4];
    const float* w_hyper = (const float*)d_in[5];
    const float* w_vis   = (const float*)d_in[6];
    const float* b_vis   = (const float*)d_in[7];
    const float* w_txt   = (const float*)d_in[8];
    const float* b_txt   = (const float*)d_in[9];
    float* out = (float*)d_out;
    const int* src = ei;
    const int* dst = ei + Ee;

    float *xemb, *cur, *nxt, *acc, *Hm, *lat;
    cudaGetSymbolAddress((void**)&xemb, g_xemb);
    cudaGetSymbolAddress((void**)&cur,  g_cur);
    cudaGetSymbolAddress((void**)&nxt,  g_nxt);
    cudaGetSymbolAddress((void**)&acc,  g_acc);
    cudaGetSymbolAddress((void**)&Hm,   g_Hm);
    cudaGetSymbolAddress((void**)&lat,  g_lat);

    const int NB = (Nn + 255) / 256;       // 196
    const int EB = (Ee + 255) / 256;       // 2344
    const int MB = (Nn + 127) / 128;       // 391
    const int WB = (Nn * 32 + 255) / 256;  // 6250

    // ---- graph normalization + CSR build ----
    init_k <<<NB, 256>>>();
    deg_k  <<<EB, 256>>>(dst);
    dinv_k <<<NB, 256>>>();
    scan1_k<<<NB, 256>>>();
    scan2_k<<<1, 32>>>(NB);
    scan3_k<<<NB, 256>>>();
    fill_k <<<EB, 256>>>(src, dst);

    // ---- x_emb = x @ w_feat + b_feat (also acc = x_emb) ----
    gemm_mma_k<<<dim3(MB, 1, 1), 256>>>(x, w_feat, b_feat, xemb, acc,
                                        Nn, HIDD, IND, IND, 0);

    // ---- logits = x_emb @ w_hyper -> g_Hm ; gumbel-softmax in place ----
    gemm_mma_k<<<dim3(MB, 2, 1), 256>>>(xemb, w_hyper, nullptr, Hm, nullptr,
                                        Nn, HYPD, HIDD, HIDD, 0);
    softmax_k<<<WB, 256>>>(gum);

    // ---- LightGCN: 3 propagation layers ----
    prop_k<<<WB, 256>>>(xemb, cur);
    prop_k<<<WB, 256>>>(cur, nxt);
    prop_k<<<WB, 256>>>(nxt, cur);

    // ---- lat = Hm^T @ x_emb  (transA + split-K + atomic epilogue) ----
    gemm_mma_k<<<dim3(2, 1, 64), 256>>>(Hm, xemb, nullptr, lat, nullptr,
                                        HYPD, HIDD, Nn, HYPD, 2 | 4);

    // ---- hyper_out = Hm @ lat -> g_nxt ----
    gemm_mma_k<<<dim3(MB, 1, 1), 256>>>(Hm, lat, nullptr, nxt, nullptr,
                                        Nn, HIDD, HYPD, HYPD, 0);

    // ---- final = acc/4 + alpha*normalize(hyper) ----
    final_k<<<WB, 256>>>(out);

    // ---- x_vision / x_text ----
    gemm_mma_k<<<dim3(MB, 1, 1), 256>>>(out, w_vis, b_vis, out + (size_t)Nn * HIDD,
                                        nullptr, Nn, HIDD, HIDD, HIDD, 1);
    gemm_mma_k<<<dim3(MB, 1, 1), 256>>>(out, w_txt, b_txt, out + (size_t)2 * Nn * HIDD,
                                        nullptr, Nn, HIDD, HIDD, HIDD, 1);
}

// round 12
// speedup vs baseline: 1.6398x; 1.6398x over previous
#include <cuda_runtime.h>
#include <cuda_bf16.h>
#include <cstdint>

#define Nn   50000
#define Ee   600000
#define IND  384
#define HIDD 128
#define HYPD 256

// ---------------- scratch (static device globals; no runtime allocation) ----------------
__device__ __align__(128) float g_xemb[(size_t)Nn * HIDD];
__device__ __align__(128) float g_cur [(size_t)Nn * HIDD];
__device__ __align__(128) float g_nxt [(size_t)Nn * HIDD];
__device__ __align__(128) float g_acc [(size_t)Nn * HIDD];
__device__ __align__(128) float g_Hm  [(size_t)Nn * HYPD];
__device__ __align__(128) float g_lat [HYPD * HIDD];
__device__ __align__(128) int   g_deg [Nn];
__device__ __align__(128) float g_dinv[Nn];
__device__ __align__(128) int   g_rowptr[Nn + 1];
__device__ __align__(128) int   g_fill[Nn];
__device__ __align__(128) int   g_col [Ee];
__device__ __align__(128) float g_val [Ee];
__device__ __align__(128) int   g_bsum[256];

// preconverted weights, stored transposed as [N][K] bf16 (hi / lo)
__device__ __align__(16) __nv_bfloat16 g_wfT[2][128 * 384];
__device__ __align__(16) __nv_bfloat16 g_whT[256 * 128];
__device__ __align__(16) __nv_bfloat16 g_wvT[2][128 * 128];
__device__ __align__(16) __nv_bfloat16 g_wtT[2][128 * 128];
__device__ __align__(16) __nv_bfloat16 g_latT[128 * 256];

__device__ __forceinline__ void split_hl(float v, unsigned short& hi, unsigned short& lo) {
    uint32_t b = __float_as_uint(v);
    uint32_t hb = b & 0xFFFF0000u;
    hi = (unsigned short)(b >> 16);
    lo = __bfloat16_as_ushort(__float2bfloat16(v - __uint_as_float(hb)));
}
__device__ __forceinline__ unsigned short bfrn(float v) {
    return __bfloat16_as_ushort(__float2bfloat16(v));
}

// ---------------- weight preconversion (one launch, 448 blocks x 256) ----------------
__global__ void wconv_k(const float* __restrict__ wf, const float* __restrict__ wh,
                        const float* __restrict__ wv, const float* __restrict__ wt) {
    int i = blockIdx.x * 256 + threadIdx.x;
    if (i < 49152) {                       // w_feat [384][128] -> [128][384] hi/lo
        int k = i >> 7, n = i & 127;
        unsigned short h, l; split_hl(wf[i], h, l);
        g_wfT[0][n * 384 + k] = __ushort_as_bfloat16(h);
        g_wfT[1][n * 384 + k] = __ushort_as_bfloat16(l);
    } else if (i < 49152 + 32768) {        // w_hyper [128][256] -> [256][128] single
        int j = i - 49152;
        int k = j >> 8, n = j & 255;
        g_whT[n * 128 + k] = __float2bfloat16(wh[j]);
    } else if (i < 49152 + 32768 + 16384) { // w_vis [128][128] -> hi/lo
        int j = i - 49152 - 32768;
        int k = j >> 7, n = j & 127;
        unsigned short h, l; split_hl(wv[j], h, l);
        g_wvT[0][n * 128 + k] = __ushort_as_bfloat16(h);
        g_wvT[1][n * 128 + k] = __ushort_as_bfloat16(l);
    } else if (i < 114688) {               // w_txt
        int j = i - 49152 - 32768 - 16384;
        int k = j >> 7, n = j & 127;
        unsigned short h, l; split_hl(wt[j], h, l);
        g_wtT[0][n * 128 + k] = __ushort_as_bfloat16(h);
        g_wtT[1][n * 128 + k] = __ushort_as_bfloat16(l);
    }
}

// lat fp32 [256][128] -> [128][256] bf16 single
__global__ void latconv_k() {
    int i = blockIdx.x * 256 + threadIdx.x;
    if (i < HYPD * HIDD) {
        int k = i >> 7, n = i & 127;
        g_latT[n * 256 + k] = __float2bfloat16(g_lat[i]);
    }
}

// ---------------- init / degree / scan / CSR fill ----------------
__global__ void init_k() {
    int i = blockIdx.x * blockDim.x + threadIdx.x;
    if (i < Nn) { g_deg[i] = 0; g_fill[i] = 0; }
    if (i < HYPD * HIDD) g_lat[i] = 0.f;
}

__global__ void deg_k(const int* __restrict__ dst) {
    int e = blockIdx.x * blockDim.x + threadIdx.x;
    if (e < Ee) atomicAdd(&g_deg[dst[e]], 1);
}

__global__ void dinv_k() {
    int i = blockIdx.x * blockDim.x + threadIdx.x;
    if (i < Nn) {
        int d = g_deg[i];
        g_dinv[i] = (d > 0) ? rsqrtf((float)d) : 0.f;
    }
}

__global__ void scan1_k() {
    __shared__ int sm[256];
    int t = threadIdx.x;
    int i = blockIdx.x * 256 + t;
    int v = (i < Nn) ? g_deg[i] : 0;
    sm[t] = v;
    __syncthreads();
    #pragma unroll
    for (int o = 1; o < 256; o <<= 1) {
        int add = (t >= o) ? sm[t - o] : 0;
        __syncthreads();
        sm[t] += add;
        __syncthreads();
    }
    if (i < Nn) g_rowptr[i] = sm[t] - v;
    if (t == 255) g_bsum[blockIdx.x] = sm[255];
}

__global__ void scan2_k(int nb) {
    if (threadIdx.x == 0 && blockIdx.x == 0) {
        int run = 0;
        for (int b = 0; b < nb; b++) { int tmp = g_bsum[b]; g_bsum[b] = run; run += tmp; }
    }
}

__global__ void scan3_k() {
    int i = blockIdx.x * blockDim.x + threadIdx.x;
    if (i < Nn) g_rowptr[i] += g_bsum[i >> 8];
    if (i == 0) g_rowptr[Nn] = Ee;
}

__global__ void fill_k(const int* __restrict__ src, const int* __restrict__ dst) {
    int e = blockIdx.x * blockDim.x + threadIdx.x;
    if (e >= Ee) return;
    int s = src[e], d = dst[e];
    int p = g_rowptr[d] + atomicAdd(&g_fill[d], 1);
    g_col[p] = s;
    g_val[p] = g_dinv[s] * g_dinv[d];
}

// =====================================================================
// Tensor-core GEMM via mma.sync, precision-tiered.
//   SPL=true : fp32-accurate 3-term bf16 hi/lo split (3 MMAs / k16)
//   SPL=false: single bf16 (1 MMA / k16)
// C[M,N] = A @ B.
// flags: 1 relu | 2 transA (A[m,k]=Aglob[k,rowBase+m]) | 4 atomic C
//      | 8 B preconverted bf16 [N][K] (B = hi ptr, Blo = lo ptr)
// gridDim.z = K-split (with flag 4). Tile BM=128 BN=128 BK=32, 8 warps.
// =====================================================================
__device__ __forceinline__ void mma16816(float* c,
    uint32_t a0, uint32_t a1, uint32_t a2, uint32_t a3,
    uint32_t b0, uint32_t b1)
{
    asm volatile(
        "mma.sync.aligned.m16n8k16.row.col.f32.bf16.bf16.f32 "
        "{%0,%1,%2,%3}, {%4,%5,%6,%7}, {%8,%9}, {%0,%1,%2,%3};"
        : "+f"(c[0]), "+f"(c[1]), "+f"(c[2]), "+f"(c[3])
        : "r"(a0), "r"(a1), "r"(a2), "r"(a3), "r"(b0), "r"(b1));
}

#define APAD 8  // row stride 40 bf16 = 20 banks -> conflict-free fragment LDS

template<bool SPL>
__global__ __launch_bounds__(256)
void gemm_mma_k(const float* __restrict__ A, const void* __restrict__ B,
                const void* __restrict__ Blo, const float* __restrict__ bias,
                float* __restrict__ C, float* __restrict__ C2,
                int M, int N, int K, int ldA, int flags)
{
    __shared__ __nv_bfloat16 As[SPL ? 2 : 1][128][32 + APAD];
    __shared__ __nv_bfloat16 Bs[SPL ? 2 : 1][128][32 + APAD];

    const int tid = threadIdx.x;
    const int wid = tid >> 5, lane = tid & 31;
    const int wm = wid >> 1;
    const int wn = wid & 1;
    const int g  = lane >> 2;
    const int tg = lane & 3;

    const int rowBase = blockIdx.x * 128;
    const int colBase = blockIdx.y * 128;
    const int nz = gridDim.z;
    const int kPer = (K + nz - 1) / nz;
    const int k0g = blockIdx.z * kPer;
    const int k1g = min(k0g + kPer, K);

    float c[2][8][4];
    #pragma unroll
    for (int mt = 0; mt < 2; mt++)
        #pragma unroll
        for (int nt = 0; nt < 8; nt++)
            #pragma unroll
            for (int q = 0; q < 4; q++) c[mt][nt][q] = 0.f;

    for (int k0 = k0g; k0 < k1g; k0 += 32) {
        // ---------------- A tile fill ----------------
        if (flags & 2) {
            int m  = tid & 127;
            int kh = (tid >> 7) * 16;
            uint32_t hp[8], lp[8];
            #pragma unroll
            for (int j = 0; j < 16; j++) {
                int gk = k0 + kh + j;
                float v = (gk < k1g) ? A[(size_t)gk * ldA + rowBase + m] : 0.f;
                unsigned short h, l;
                if constexpr (SPL) split_hl(v, h, l);
                else { h = bfrn(v); l = 0; }
                if ((j & 1) == 0) { hp[j >> 1] = h; lp[j >> 1] = l; }
                else { hp[j >> 1] |= (uint32_t)h << 16; lp[j >> 1] |= (uint32_t)l << 16; }
            }
            *(uint2*)&As[0][m][kh]      = make_uint2(hp[0], hp[1]);
            *(uint2*)&As[0][m][kh + 4]  = make_uint2(hp[2], hp[3]);
            *(uint2*)&As[0][m][kh + 8]  = make_uint2(hp[4], hp[5]);
            *(uint2*)&As[0][m][kh + 12] = make_uint2(hp[6], hp[7]);
            if constexpr (SPL) {
                *(uint2*)&As[1][m][kh]      = make_uint2(lp[0], lp[1]);
                *(uint2*)&As[1][m][kh + 4]  = make_uint2(lp[2], lp[3]);
                *(uint2*)&As[1][m][kh + 8]  = make_uint2(lp[4], lp[5]);
                *(uint2*)&As[1][m][kh + 12] = make_uint2(lp[6], lp[7]);
            }
        } else {
            #pragma unroll
            for (int i = 0; i < 4; i++) {
                int f = tid + i * 256;
                int r = f >> 3, q = f & 7;
                int grow = rowBase + r;
                float4 v = make_float4(0.f, 0.f, 0.f, 0.f);
                if (grow < M && (k0 + q * 4 + 3) < k1g)
                    v = *(const float4*)(A + (size_t)grow * ldA + k0 + q * 4);
                if constexpr (SPL) {
                    unsigned short h0,h1,h2,h3,l0,l1,l2,l3;
                    split_hl(v.x,h0,l0); split_hl(v.y,h1,l1);
                    split_hl(v.z,h2,l2); split_hl(v.w,h3,l3);
                    *(uint2*)&As[0][r][q*4] = make_uint2(h0 | ((uint32_t)h1<<16), h2 | ((uint32_t)h3<<16));
                    *(uint2*)&As[1][r][q*4] = make_uint2(l0 | ((uint32_t)l1<<16), l2 | ((uint32_t)l3<<16));
                } else {
                    unsigned short h0 = bfrn(v.x), h1 = bfrn(v.y), h2 = bfrn(v.z), h3 = bfrn(v.w);
                    *(uint2*)&As[0][r][q*4] = make_uint2(h0 | ((uint32_t)h1<<16), h2 | ((uint32_t)h3<<16));
                }
            }
        }
        // ---------------- B tile fill ----------------
        if (flags & 8) {
            int nl = tid & 127, kh = (tid >> 7) * 16;
            const __nv_bfloat16* bh = (const __nv_bfloat16*)B;
            size_t bo = (size_t)(colBase + nl) * K + k0 + kh;
            uint4 vh0 = *(const uint4*)(bh + bo);
            uint4 vh1 = *(const uint4*)(bh + bo + 8);
            *(uint2*)&Bs[0][nl][kh]      = make_uint2(vh0.x, vh0.y);
            *(uint2*)&Bs[0][nl][kh + 4]  = make_uint2(vh0.z, vh0.w);
            *(uint2*)&Bs[0][nl][kh + 8]  = make_uint2(vh1.x, vh1.y);
            *(uint2*)&Bs[0][nl][kh + 12] = make_uint2(vh1.z, vh1.w);
            if constexpr (SPL) {
                const __nv_bfloat16* bl = (const __nv_bfloat16*)Blo;
                uint4 vl0 = *(const uint4*)(bl + bo);
                uint4 vl1 = *(const uint4*)(bl + bo + 8);
                *(uint2*)&Bs[1][nl][kh]      = make_uint2(vl0.x, vl0.y);
                *(uint2*)&Bs[1][nl][kh + 4]  = make_uint2(vl0.z, vl0.w);
                *(uint2*)&Bs[1][nl][kh + 8]  = make_uint2(vl1.x, vl1.y);
                *(uint2*)&Bs[1][nl][kh + 12] = make_uint2(vl1.z, vl1.w);
            }
        } else {
            int nl = tid & 127, kh = (tid >> 7) * 16;
            const float* Bf = (const float*)B;
            uint32_t hp[8], lp[8];
            #pragma unroll
            for (int j = 0; j < 16; j++) {
                int gk = k0 + kh + j;
                float v = (gk < k1g) ? Bf[(size_t)gk * N + colBase + nl] : 0.f;
                unsigned short h, l;
                if constexpr (SPL) split_hl(v, h, l);
                else { h = bfrn(v); l = 0; }
                if ((j & 1) == 0) { hp[j >> 1] = h; lp[j >> 1] = l; }
                else { hp[j >> 1] |= (uint32_t)h << 16; lp[j >> 1] |= (uint32_t)l << 16; }
            }
            *(uint2*)&Bs[0][nl][kh]      = make_uint2(hp[0], hp[1]);
            *(uint2*)&Bs[0][nl][kh + 4]  = make_uint2(hp[2], hp[3]);
            *(uint2*)&Bs[0][nl][kh + 8]  = make_uint2(hp[4], hp[5]);
            *(uint2*)&Bs[0][nl][kh + 12] = make_uint2(hp[6], hp[7]);
            if constexpr (SPL) {
                *(uint2*)&Bs[1][nl][kh]      = make_uint2(lp[0], lp[1]);
                *(uint2*)&Bs[1][nl][kh + 4]  = make_uint2(lp[2], lp[3]);
                *(uint2*)&Bs[1][nl][kh + 8]  = make_uint2(lp[4], lp[5]);
                *(uint2*)&Bs[1][nl][kh + 12] = make_uint2(lp[6], lp[7]);
            }
        }
        __syncthreads();

        // ---------------- compute ----------------
        #pragma unroll
        for (int kk = 0; kk < 2; kk++) {
            const int kb = kk * 16 + tg * 2;
            uint32_t ah[2][4], al[2][4];
            #pragma unroll
            for (int mt = 0; mt < 2; mt++) {
                int r0 = wm * 32 + mt * 16 + g;
                ah[mt][0] = *(const uint32_t*)&As[0][r0    ][kb];
                ah[mt][1] = *(const uint32_t*)&As[0][r0 + 8][kb];
                ah[mt][2] = *(const uint32_t*)&As[0][r0    ][kb + 8];
                ah[mt][3] = *(const uint32_t*)&As[0][r0 + 8][kb + 8];
                if constexpr (SPL) {
                    al[mt][0] = *(const uint32_t*)&As[1][r0    ][kb];
                    al[mt][1] = *(const uint32_t*)&As[1][r0 + 8][kb];
                    al[mt][2] = *(const uint32_t*)&As[1][r0    ][kb + 8];
                    al[mt][3] = *(const uint32_t*)&As[1][r0 + 8][kb + 8];
                }
            }
            #pragma unroll
            for (int nt = 0; nt < 8; nt++) {
                int nr = wn * 64 + nt * 8 + g;
                uint32_t bh0 = *(const uint32_t*)&Bs[0][nr][kb];
                uint32_t bh1 = *(const uint32_t*)&Bs[0][nr][kb + 8];
                #pragma unroll
                for (int mt = 0; mt < 2; mt++)
                    mma16816(c[mt][nt], ah[mt][0], ah[mt][1], ah[mt][2], ah[mt][3], bh0, bh1);
                if constexpr (SPL) {
                    uint32_t bl0 = *(const uint32_t*)&Bs[1][nr][kb];
                    uint32_t bl1 = *(const uint32_t*)&Bs[1][nr][kb + 8];
                    #pragma unroll
                    for (int mt = 0; mt < 2; mt++) {
                        mma16816(c[mt][nt], al[mt][0], al[mt][1], al[mt][2], al[mt][3], bh0, bh1);
                        mma16816(c[mt][nt], ah[mt][0], ah[mt][1], ah[mt][2], ah[mt][3], bl0, bl1);
                    }
                }
            }
        }
        __syncthreads();
    }

    // ---------------- epilogue ----------------
    const bool doRelu = (flags & 1), doAtom = (flags & 4);
    #pragma unroll
    for (int mt = 0; mt < 2; mt++) {
        #pragma unroll
        for (int half = 0; half < 2; half++) {
            int grow = rowBase + wm * 32 + mt * 16 + g + half * 8;
            if (grow >= M) continue;
            #pragma unroll
            for (int nt = 0; nt < 8; nt++) {
                int col = colBase + wn * 64 + nt * 8 + tg * 2;
                float v0 = c[mt][nt][half * 2 + 0];
                float v1 = c[mt][nt][half * 2 + 1];
                if (doAtom) {
                    atomicAdd(C + (size_t)grow * N + col,     v0);
                    atomicAdd(C + (size_t)grow * N + col + 1, v1);
                } else {
                    if (bias) { v0 += bias[col]; v1 += bias[col + 1]; }
                    if (doRelu) { v0 = fmaxf(v0, 0.f); v1 = fmaxf(v1, 0.f); }
                    float2 o = make_float2(v0, v1);
                    *(float2*)(C + (size_t)grow * N + col) = o;
                    if (C2) *(float2*)(C2 + (size_t)grow * N + col) = o;
                }
            }
        }
    }
}

// ---------------- gumbel-softmax, MUFU-based (warp per row, in-place) ----------------
// t = 2*logit - 2*ln(L), L = -ln(u+eps)+eps. For u>0.875 use 3-term series for -ln(u)
// (MUFU lg2 abs-error ~2^-22 would be relatively large there).
__global__ void softmax_k(const float* __restrict__ gum) {
    int row  = (blockIdx.x * blockDim.x + threadIdx.x) >> 5;
    int lane = threadIdx.x & 31;
    if (row >= Nn) return;
    const float* lrow = g_Hm + (size_t)row * HYPD;
    const float* urow = gum  + (size_t)row * HYPD;
    float t[8];
    #pragma unroll
    for (int q = 0; q < 2; q++) {
        float4 lg = *(const float4*)(lrow + lane * 8 + q * 4);
        float4 uu = *(const float4*)(urow + lane * 8 + q * 4);
        float lv[4] = {lg.x, lg.y, lg.z, lg.w};
        float uv[4] = {uu.x, uu.y, uu.z, uu.w};
        #pragma unroll
        for (int j = 0; j < 4; j++) {
            float up = uv[j] + 1e-10f;
            float x  = up - 1.0f;
            float l2u;
            asm("lg2.approx.ftz.f32 %0, %1;" : "=f"(l2u) : "f"(up));
            float Lm = -0.69314718f * l2u;
            float Ls = -(x * (1.f + x * (-0.5f + x * 0.33333333f)));
            float L  = (x > -0.125f) ? Ls : Lm;
            L += 1e-10f;
            float p2;
            asm("lg2.approx.ftz.f32 %0, %1;" : "=f"(p2) : "f"(L));
            t[q * 4 + j] = 2.f * lv[j] - 1.38629436f * p2;
        }
    }
    float m = t[0];
    #pragma unroll
    for (int j = 1; j < 8; j++) m = fmaxf(m, t[j]);
    #pragma unroll
    for (int o = 16; o; o >>= 1) m = fmaxf(m, __shfl_xor_sync(0xffffffffu, m, o));
    float s = 0.f;
    #pragma unroll
    for (int j = 0; j < 8; j++) {
        float e;
        asm("ex2.approx.ftz.f32 %0, %1;" : "=f"(e) : "f"((t[j] - m) * 1.44269504f));
        t[j] = e; s += e;
    }
    #pragma unroll
    for (int o = 16; o; o >>= 1) s += __shfl_xor_sync(0xffffffffu, s, o);
    float inv = 1.f / s;
    float* orow = g_Hm + (size_t)row * HYPD;
    #pragma unroll
    for (int q = 0; q < 2; q++) {
        float4 v = make_float4(t[q*4+0]*inv, t[q*4+1]*inv, t[q*4+2]*inv, t[q*4+3]*inv);
        *(float4*)(orow + lane * 8 + q * 4) = v;
    }
}

// ---------------- LightGCN propagation: warp per dst row, CSR gather ----------------
__global__ void prop_k(const float* __restrict__ cur, float* __restrict__ nxt) {
    int row  = (blockIdx.x * blockDim.x + threadIdx.x) >> 5;
    int lane = threadIdx.x & 31;
    if (row >= Nn) return;
    int s = g_rowptr[row], e = g_rowptr[row + 1];
    float4 a = make_float4(0.f, 0.f, 0.f, 0.f);
    for (int p = s; p < e; p++) {
        float w = g_val[p];
        int   c = g_col[p];
        float4 v = *(const float4*)(cur + (size_t)c * HIDD + lane * 4);
        a.x += w * v.x; a.y += w * v.y; a.z += w * v.z; a.w += w * v.w;
    }
    size_t off = (size_t)row * HIDD + lane * 4;
    *(float4*)(nxt + off) = a;
    float4 ac = *(float4*)(g_acc + off);
    ac.x += a.x; ac.y += a.y; ac.z += a.z; ac.w += a.w;
    *(float4*)(g_acc + off) = ac;
}

// ---------------- final = acc/4 + alpha * hyper/||hyper|| ----------------
__global__ void final_k(float* __restrict__ out) {
    int row  = (blockIdx.x * blockDim.x + threadIdx.x) >> 5;
    int lane = threadIdx.x & 31;
    if (row >= Nn) return;
    size_t off = (size_t)row * HIDD + lane * 4;
    float4 h = *(const float4*)(g_nxt + off);
    float ss = h.x * h.x + h.y * h.y + h.z * h.z + h.w * h.w;
    #pragma unroll
    for (int o = 16; o; o >>= 1) ss += __shfl_xor_sync(0xffffffffu, ss, o);
    float inv = 0.1f / fmaxf(sqrtf(ss), 1e-12f);
    float4 a = *(const float4*)(g_acc + off);
    float4 r;
    r.x = a.x * 0.25f + h.x * inv;
    r.y = a.y * 0.25f + h.y * inv;
    r.z = a.z * 0.25f + h.z * inv;
    r.w = a.w * 0.25f + h.w * inv;
    *(float4*)(out + off) = r;
}

// ---------------- launcher ----------------
extern "C" void kernel_launch(void* const* d_in, const int* in_sizes, int n_in,
                              void* d_out, int out_size) {
    const float* x       = (const float*)d_in[0];
    const int*   ei      = (const int*)  d_in[1];
    const float* gum     = (const float*)d_in[2];
    const float* w_feat  = (const float*)d_in[3];
    const float* b_feat  = (const float*)d_in[4];
    const float* w_hyper = (const float*)d_in[5];
    const float* w_vis   = (const float*)d_in[6];
    const float* b_vis   = (const float*)d_in[7];
    const float* w_txt   = (const float*)d_in[8];
    const float* b_txt   = (const float*)d_in[9];
    float* out = (float*)d_out;
    const int* src = ei;
    const int* dst = ei + Ee;

    float *xemb, *cur, *nxt, *acc, *Hm, *lat;
    cudaGetSymbolAddress((void**)&xemb, g_xemb);
    cudaGetSymbolAddress((void**)&cur,  g_cur);
    cudaGetSymbolAddress((void**)&nxt,  g_nxt);
    cudaGetSymbolAddress((void**)&acc,  g_acc);
    cudaGetSymbolAddress((void**)&Hm,   g_Hm);
    cudaGetSymbolAddress((void**)&lat,  g_lat);
    void *wfT_hi, *wfT_lo, *whT, *wvT_hi, *wvT_lo, *wtT_hi, *wtT_lo, *latT;
    cudaGetSymbolAddress(&wfT_hi, g_wfT);  wfT_lo = (char*)wfT_hi + 128 * 384 * 2;
    cudaGetSymbolAddress(&whT,    g_whT);
    cudaGetSymbolAddress(&wvT_hi, g_wvT);  wvT_lo = (char*)wvT_hi + 128 * 128 * 2;
    cudaGetSymbolAddress(&wtT_hi, g_wtT);  wtT_lo = (char*)wtT_hi + 128 * 128 * 2;
    cudaGetSymbolAddress(&latT,   g_latT);

    const int NB = (Nn + 255) / 256;       // 196
    const int EB = (Ee + 255) / 256;       // 2344
    const int MB = (Nn + 127) / 128;       // 391
    const int WB = (Nn * 32 + 255) / 256;  // 6250

    // 1: weight preconversion
    wconv_k<<<448, 256>>>(w_feat, w_hyper, w_vis, w_txt);
    // 2-5: graph norm prologue
    init_k <<<NB, 256>>>();
    deg_k  <<<EB, 256>>>(dst);
    dinv_k <<<NB, 256>>>();
    scan1_k<<<NB, 256>>>();
    // 6 (profiled by ncu -s 5 -c 1): x_emb = x @ w_feat + b_feat  (SPLIT, pre-B)
    gemm_mma_k<true><<<dim3(MB, 1, 1), 256>>>(x, wfT_hi, wfT_lo, b_feat, xemb, acc,
                                              Nn, HIDD, IND, IND, 8);
    // 7-9: finish CSR build
    scan2_k<<<1, 32>>>(NB);
    scan3_k<<<NB, 256>>>();
    fill_k <<<EB, 256>>>(src, dst);

    // logits = x_emb @ w_hyper (FAST, pre-B) ; gumbel-softmax in place
    gemm_mma_k<false><<<dim3(MB, 2, 1), 256>>>(xemb, whT, nullptr, nullptr, Hm, nullptr,
                                               Nn, HYPD, HIDD, HIDD, 8);
    softmax_k<<<WB, 256>>>(gum);

    // LightGCN: 3 propagation layers
    prop_k<<<WB, 256>>>(xemb, cur);
    prop_k<<<WB, 256>>>(cur, nxt);
    prop_k<<<WB, 256>>>(nxt, cur);

    // lat = Hm^T @ x_emb (FAST, transA + split-K + atomic)
    gemm_mma_k<false><<<dim3(2, 1, 64), 256>>>(Hm, xemb, nullptr, nullptr, lat, nullptr,
                                               HYPD, HIDD, Nn, HYPD, 2 | 4);
    latconv_k<<<128, 256>>>();

    // hyper_out = Hm @ lat (FAST, pre-B) -> g_nxt
    gemm_mma_k<false><<<dim3(MB, 1, 1), 256>>>(Hm, latT, nullptr, nullptr, nxt, nullptr,
                                               Nn, HIDD, HYPD, HYPD, 8);

    // final = acc/4 + alpha*normalize(hyper)
    final_k<<<WB, 256>>>(out);

    // x_vision / x_text (SPLIT, pre-B, relu)
    gemm_mma_k<true><<<dim3(MB, 1, 1), 256>>>(out, wvT_hi, wvT_lo, b_vis,
                                              out + (size_t)Nn * HIDD, nullptr,
                                              Nn, HIDD, HIDD, HIDD, 1 | 8);
    gemm_mma_k<true><<<dim3(MB, 1, 1), 256>>>(out, wtT_hi, wtT_lo, b_txt,
                                              out + (size_t)2 * Nn * HIDD, nullptr,
                                              Nn, HIDD, HIDD, HIDD, 1 | 8);
}